// round 10
// baseline (speedup 1.0000x reference)
#include <cuda_runtime.h>
#include <math.h>

#define NELEM  16384
#define KSEL   8192
#define NC1    64
#define T1     256
#define NC2    64
#define T2     256
#define NW2    (T2 / 32)
#define NBINS  16384
#define SH     12
#define LOBITS 0x3B800000u   // float bits of 2^-8; lower scores clamp to bin 0

// ---- persistent scratch (zero-init at load; maintained across graph replays) ----
// Histogram + boundary counters double-buffered by launch parity. Launch L uses
// buffer p=L&1; its K1 zeroes buffer p^1 for launch L+1 (whose previous reader,
// launch L-1's K2, finished before this K1 by stream order).
__device__ __align__(16) unsigned int g_hist[2][NBINS];
__device__ uint2        g_cand[NELEM];
__device__ unsigned int g_ticket[2];
__device__ unsigned int g_done[2];
__device__ unsigned int g_l1;   // monotonic launch tickets (parity sources)
__device__ unsigned int g_l2;

__device__ __forceinline__ unsigned int ld_acq(const unsigned int* p) {
    unsigned int v;
    asm volatile("ld.acquire.gpu.u32 %0, [%1];" : "=r"(v) : "l"(p) : "memory");
    return v;
}
__device__ __forceinline__ void red_rel_add(unsigned int* p, unsigned int v) {
    asm volatile("red.release.gpu.global.add.u32 [%0], %1;" :: "l"(p), "r"(v) : "memory");
}

__device__ __forceinline__ int score_bin(unsigned int v) {
    const int d = (int)(v - LOBITS);
    int bin = d < 0 ? 0 : (d >> SH);
    return bin < NBINS - 1 ? bin : NBINS - 1;
}

// ================= K1: conv + sigmoid + score store + histogram =================
__global__ __launch_bounds__(T1, 1)
void ca_k1(const float* __restrict__ x,
           const float* __restrict__ w7,
           float* __restrict__ out)
{
    __shared__ float        sx[T1 + 6];
    __shared__ float        swt[7];
    __shared__ unsigned int s_par;

    const int tid = threadIdx.x;
    const int E0  = (int)blockIdx.x * T1;
    const int gid = E0 + tid;

    if (tid == 0) s_par = (atomicAdd(&g_l1, 1u) / NC1) & 1u;
    if (tid < 7)  swt[tid] = __ldg(w7 + tid);

    sx[3 + tid] = __ldg(x + gid);
    if (tid < 3) {
        const int gl = E0 - 3 + tid;
        sx[tid] = (gl >= 0) ? __ldg(x + gl) : 0.0f;
        const int gr = E0 + T1 + tid;
        sx[3 + T1 + tid] = (gr < NELEM) ? __ldg(x + gr) : 0.0f;
    }
    __syncthreads();
    const unsigned int par = s_par;

    float y = sx[tid] * swt[0];
    y = fmaf(sx[tid + 1], swt[1], y);
    y = fmaf(sx[tid + 2], swt[2], y);
    y = fmaf(sx[tid + 3], swt[3], y);
    y = fmaf(sx[tid + 4], swt[4], y);
    y = fmaf(sx[tid + 5], swt[5], y);
    y = fmaf(sx[tid + 6], swt[6], y);

    const float s = 1.0f / (1.0f + expf(-y));
    out[NELEM + gid] = s;                          // attention_score output

    const unsigned int v = __float_as_uint(s);     // positive: bit order == value order
    atomicAdd(&g_hist[par][score_bin(v)], 1u);     // RED, spread addresses

    // prepare next launch's buffer (untouched during this launch)
    g_hist[par ^ 1u][gid] = 0u;                    // 16384 threads x 1 bin
    if (gid == 0) { g_ticket[par ^ 1u] = 0u; g_done[par ^ 1u] = 0u; }
}

// ================= K2: redundant scan + select + emit =================
__global__ __launch_bounds__(T2, 1)
void ca_k2(const float* __restrict__ x,
           float* __restrict__ out)
{
    __shared__ unsigned int sm_w[NW2];
    __shared__ unsigned int s_par, s_w0, s_w1;

    const int tid  = threadIdx.x;
    const int lane = tid & 31;
    const int wid  = tid >> 5;
    const int gid  = (int)blockIdx.x * T2 + tid;

    if (tid == 0) s_par = (atomicAdd(&g_l2, 1u) / NC2) & 1u;
    __syncthreads();
    const unsigned int  par  = s_par;
    const unsigned int* hist = g_hist[par];

    // ---- per-thread sum of 64 bins (hist is L2-hot from K1) ----
    unsigned int local = 0;
    {
        const uint4* hp = (const uint4*)(hist + tid * 64);
        #pragma unroll
        for (int q = 0; q < 16; ++q) {
            const uint4 u = __ldcg(hp + q);
            local += u.x + u.y + u.z + u.w;
        }
    }
    // ---- block exclusive scan (all 32 lanes participate in every shuffle) ----
    unsigned int inc = local;
    #pragma unroll
    for (int o = 1; o < 32; o <<= 1) {
        unsigned int t = __shfl_up_sync(0xffffffffu, inc, o);
        if (lane >= o) inc += t;
    }
    if (lane == 31) sm_w[wid] = inc;
    __syncthreads();
    if (wid == 0) {
        unsigned int wsum = (lane < NW2) ? sm_w[lane] : 0u;   // pad with 0
        unsigned int winc = wsum;
        #pragma unroll
        for (int o = 1; o < 32; o <<= 1) {
            unsigned int t = __shfl_up_sync(0xffffffffu, winc, o);
            if (lane >= o) winc += t;
        }
        if (lane < NW2) sm_w[lane] = winc - wsum;             // exclusive warp base
    }
    __syncthreads();
    const unsigned int base = sm_w[wid] + inc - local;

    if (base < KSEL && base + local >= KSEL) {     // exactly one thread
        unsigned int c = base;
        #pragma unroll 1
        for (int q = 0; q < 64; ++q) {
            const unsigned int hq = __ldcg(&hist[tid * 64 + q]);
            if (c + hq >= KSEL) {
                s_w0 = (unsigned)(tid * 64 + q) | ((KSEL - c) << 16);  // bstar | jkeep<<16
                s_w1 = hq;                                              // hcount
                break;
            }
            c += hq;
        }
    }
    __syncthreads();
    const int          bstar  = (int)(s_w0 & 0xFFFFu);
    const unsigned int jkeep  = s_w0 >> 16;
    const unsigned int hcount = s_w1;

    // ---- per-element decision (s re-read from K1's store; L1 flushed per launch) ----
    const float s  = out[NELEM + gid];
    const float xi = __ldg(x + gid);
    const unsigned int v = __float_as_uint(s);
    const int bin = score_bin(v);

    if (bin != bstar) {
        out[gid] = (bin < bstar) ? xi * (s + 1.0f) : 0.0f;
    } else {
        // register, release, wait for all hcount registrants, exact stable rank
        const unsigned int t = atomicAdd(&g_ticket[par], 1u);
        g_cand[t] = make_uint2(v, (unsigned int)gid);
        red_rel_add(&g_done[par], 1u);

        bool full = true;
        unsigned int spins = 0;
        while (ld_acq(&g_done[par]) < hcount) {
            if (++spins > (1u << 22)) { full = false; break; }   // safety valve
        }

        unsigned int rank = 0;
        if (full) {
            for (unsigned int c = 0; c < hcount; ++c) {
                const uint2 cd = __ldcg(&g_cand[c]);
                rank += (cd.x < v) || (cd.x == v && cd.y < (unsigned int)gid);
            }
        } else {
            // fallback: exact rank from the full score array (same result)
            for (int j = 0; j < NELEM; ++j) {
                const unsigned int vj = __float_as_uint(out[NELEM + j]);
                if (score_bin(vj) == bstar)
                    rank += (vj < v) || (vj == v && j < gid);
            }
        }
        out[gid] = (rank < jkeep) ? xi * (s + 1.0f) : 0.0f;
    }
}

extern "C" void kernel_launch(void* const* d_in, const int* in_sizes, int n_in,
                              void* d_out, int out_size)
{
    const float* x = (const float*)d_in[0];
    const float* w = (const float*)d_in[1];
    if (n_in >= 2 && in_sizes[0] == 7) {   // defensive input-order check
        const float* t = x; x = w; w = t;
    }
    float* out = (float*)d_out;

    ca_k1<<<NC1, T1>>>(x, w, out);
    ca_k2<<<NC2, T2>>>(x, out);
}

// round 11
// speedup vs baseline: 1.7690x; 1.7690x over previous
#include <cuda_runtime.h>
#include <math.h>

#define NELEM  16384
#define KSEL   8192
#define NC1    64
#define T1     256
#define NC2    16
#define T2     1024
#define NW2    (T2 / 32)
#define NBINS  16384
#define SH     12
#define LOBITS 0x3B800000u   // float bits of 2^-8; lower scores clamp to bin 0

// ---- persistent scratch (zero-init at load; maintained across graph replays) ----
// Histogram + boundary counters double-buffered by launch parity. Launch L uses
// buffer p=L&1; its K1 zeroes buffer p^1 for launch L+1 (whose previous reader,
// launch L-1's K2, finished before this K1 by stream order).
__device__ __align__(16) unsigned int g_hist[2][NBINS];
__device__ uint2        g_cand[NELEM];
__device__ unsigned int g_ticket[2];
__device__ unsigned int g_done[2];
__device__ unsigned int g_l1;   // monotonic launch tickets (parity sources)
__device__ unsigned int g_l2;

__device__ __forceinline__ unsigned int ld_acq(const unsigned int* p) {
    unsigned int v;
    asm volatile("ld.acquire.gpu.u32 %0, [%1];" : "=r"(v) : "l"(p) : "memory");
    return v;
}
__device__ __forceinline__ void red_rel_add(unsigned int* p, unsigned int v) {
    asm volatile("red.release.gpu.global.add.u32 [%0], %1;" :: "l"(p), "r"(v) : "memory");
}

__device__ __forceinline__ int score_bin(unsigned int v) {
    const int d = (int)(v - LOBITS);
    int bin = d < 0 ? 0 : (d >> SH);
    return bin < NBINS - 1 ? bin : NBINS - 1;
}

// ================= K1: conv + sigmoid + score store + histogram =================
__global__ __launch_bounds__(T1, 1)
void ca_k1(const float* __restrict__ x,
           const float* __restrict__ w7,
           float* __restrict__ out)
{
    __shared__ float        sx[T1 + 6];
    __shared__ float        swt[7];
    __shared__ unsigned int s_par;

    const int tid = threadIdx.x;
    const int E0  = (int)blockIdx.x * T1;
    const int gid = E0 + tid;

    if (tid == 0) s_par = (atomicAdd(&g_l1, 1u) / NC1) & 1u;
    if (tid < 7)  swt[tid] = __ldg(w7 + tid);

    sx[3 + tid] = __ldg(x + gid);
    if (tid < 3) {
        const int gl = E0 - 3 + tid;
        sx[tid] = (gl >= 0) ? __ldg(x + gl) : 0.0f;
        const int gr = E0 + T1 + tid;
        sx[3 + T1 + tid] = (gr < NELEM) ? __ldg(x + gr) : 0.0f;
    }
    __syncthreads();
    const unsigned int par = s_par;

    float y = sx[tid] * swt[0];
    y = fmaf(sx[tid + 1], swt[1], y);
    y = fmaf(sx[tid + 2], swt[2], y);
    y = fmaf(sx[tid + 3], swt[3], y);
    y = fmaf(sx[tid + 4], swt[4], y);
    y = fmaf(sx[tid + 5], swt[5], y);
    y = fmaf(sx[tid + 6], swt[6], y);

    const float s = 1.0f / (1.0f + expf(-y));
    out[NELEM + gid] = s;                          // attention_score output

    const unsigned int v = __float_as_uint(s);     // positive: bit order == value order
    atomicAdd(&g_hist[par][score_bin(v)], 1u);     // RED, spread addresses

    // prepare next launch's buffer (untouched during this launch)
    g_hist[par ^ 1u][gid] = 0u;                    // 16384 threads x 1 bin
    if (gid == 0) { g_ticket[par ^ 1u] = 0u; g_done[par ^ 1u] = 0u; }
}

// ================= K2: redundant register-resident scan + select + emit =================
__global__ __launch_bounds__(T2, 1)
void ca_k2(const float* __restrict__ x,
           float* __restrict__ out)
{
    __shared__ unsigned int sm_w[NW2];
    __shared__ unsigned int s_par, s_w0, s_w1;

    const int tid  = threadIdx.x;
    const int lane = tid & 31;
    const int wid  = tid >> 5;
    const int gid  = (int)blockIdx.x * T2 + tid;

    if (tid == 0) s_par = (atomicAdd(&g_l2, 1u) / NC2) & 1u;
    __syncthreads();
    const unsigned int  par  = s_par;
    const unsigned int* hist = g_hist[par];

    // ---- 16 bins/thread, kept in REGISTERS (4 independent uint4 loads) ----
    unsigned int h[16];
    {
        const uint4* hp = (const uint4*)(hist + tid * 16);
        const uint4 q0 = __ldcg(hp + 0), q1 = __ldcg(hp + 1),
                    q2 = __ldcg(hp + 2), q3 = __ldcg(hp + 3);
        h[0]=q0.x;  h[1]=q0.y;  h[2]=q0.z;  h[3]=q0.w;
        h[4]=q1.x;  h[5]=q1.y;  h[6]=q1.z;  h[7]=q1.w;
        h[8]=q2.x;  h[9]=q2.y;  h[10]=q2.z; h[11]=q2.w;
        h[12]=q3.x; h[13]=q3.y; h[14]=q3.z; h[15]=q3.w;
    }
    unsigned int local = 0;
    #pragma unroll
    for (int q = 0; q < 16; ++q) local += h[q];

    // ---- block exclusive scan (all 32 lanes active in every shuffle) ----
    unsigned int inc = local;
    #pragma unroll
    for (int o = 1; o < 32; o <<= 1) {
        unsigned int t = __shfl_up_sync(0xffffffffu, inc, o);
        if (lane >= o) inc += t;
    }
    if (lane == 31) sm_w[wid] = inc;
    __syncthreads();
    if (wid == 0) {
        unsigned int wsum = sm_w[lane];          // NW2 == 32
        unsigned int winc = wsum;
        #pragma unroll
        for (int o = 1; o < 32; o <<= 1) {
            unsigned int t = __shfl_up_sync(0xffffffffu, winc, o);
            if (lane >= o) winc += t;
        }
        sm_w[lane] = winc - wsum;                // exclusive warp base
    }
    __syncthreads();
    const unsigned int base = sm_w[wid] + inc - local;

    if (base < KSEL && base + local >= KSEL) {   // exactly one thread; registers only
        unsigned int c = base;
        #pragma unroll
        for (int q = 0; q < 16; ++q) {
            if (c + h[q] >= KSEL) {
                s_w0 = (unsigned)(tid * 16 + q) | ((KSEL - c) << 16);  // bstar | jkeep<<16
                s_w1 = h[q];                                            // hcount
                break;
            }
            c += h[q];
        }
    }
    __syncthreads();
    const int          bstar  = (int)(s_w0 & 0xFFFFu);
    const unsigned int jkeep  = s_w0 >> 16;
    const unsigned int hcount = s_w1;

    // ---- per-element decision (s re-read from K1's store; L2-hot, L1 fresh) ----
    const float s  = out[NELEM + gid];
    const float xi = __ldg(x + gid);
    const unsigned int v = __float_as_uint(s);
    const int bin = score_bin(v);

    if (bin != bstar) {
        out[gid] = (bin < bstar) ? xi * (s + 1.0f) : 0.0f;
    } else {
        // register, release, wait for all hcount registrants, exact stable rank
        const unsigned int t = atomicAdd(&g_ticket[par], 1u);
        g_cand[t] = make_uint2(v, (unsigned int)gid);
        red_rel_add(&g_done[par], 1u);

        bool full = true;
        unsigned int spins = 0;
        while (ld_acq(&g_done[par]) < hcount) {
            if (++spins > (1u << 22)) { full = false; break; }   // safety valve
        }

        unsigned int rank = 0;
        if (full) {
            for (unsigned int c = 0; c < hcount; ++c) {
                const uint2 cd = __ldcg(&g_cand[c]);
                rank += (cd.x < v) || (cd.x == v && cd.y < (unsigned int)gid);
            }
        } else {
            // fallback: exact rank from the full score array (same result)
            for (int j = 0; j < NELEM; ++j) {
                const unsigned int vj = __float_as_uint(out[NELEM + j]);
                if (score_bin(vj) == bstar)
                    rank += (vj < v) || (vj == v && j < gid);
            }
        }
        out[gid] = (rank < jkeep) ? xi * (s + 1.0f) : 0.0f;
    }
}

extern "C" void kernel_launch(void* const* d_in, const int* in_sizes, int n_in,
                              void* d_out, int out_size)
{
    const float* x = (const float*)d_in[0];
    const float* w = (const float*)d_in[1];
    if (n_in >= 2 && in_sizes[0] == 7) {   // defensive input-order check
        const float* t = x; x = w; w = t;
    }
    float* out = (float*)d_out;

    ca_k1<<<NC1, T1>>>(x, w, out);
    ca_k2<<<NC2, T2>>>(x, out);
}